// round 13
// baseline (speedup 1.0000x reference)
#include <cuda_runtime.h>
#include <cuda_fp16.h>
#include <math.h>
#include <stdint.h>

// ---------------- problem constants ----------------
constexpr int cH   = 16;
constexpr int cDH  = 128;
constexpr int cRK  = 512;
constexpr int cRD  = 64;
constexpr int cB   = 2;
constexpr int cL   = 2048;
constexpr int cE   = 2048;
constexpr int cDQK = cDH + cRD;          // 192
constexpr int cNQ  = cH * cDQK;          // 3072
constexpr int cNKV = cRK + cRD;          // 576
constexpr int cNUP = cH * (2*cDH + cRD); // 5120 (per-head block of 320)
constexpr int cM   = cB * cL;            // 4096
constexpr int cBH  = cB * cH;            // 32

// ---------------- scratch (half everywhere) ----------------
__device__ __half g_xh   [(size_t)cM * cE];
__device__ __half g_wqT  [(size_t)cNQ * cE];
__device__ __half g_wkvT [(size_t)cNKV * cE];
__device__ __half g_wupT [(size_t)cNUP * cRK];
__device__ __half g_woT  [(size_t)cE * cNQ];
__device__ __half g_qallh[(size_t)cM * cNQ];
__device__ __half g_kvh  [(size_t)cM * cNKV];
__device__ __half g_uph  [(size_t)cM * cNUP];
__device__ __half g_AOh  [(size_t)cM * cNQ];

// ---------------- low-level helpers ----------------
__device__ __forceinline__ void mma_f16(float* d, const uint32_t* a, const uint32_t* b) {
    asm volatile(
        "mma.sync.aligned.m16n8k16.row.col.f32.f16.f16.f32 "
        "{%0,%1,%2,%3},{%4,%5,%6,%7},{%8,%9},{%0,%1,%2,%3};"
        : "+f"(d[0]), "+f"(d[1]), "+f"(d[2]), "+f"(d[3])
        : "r"(a[0]), "r"(a[1]), "r"(a[2]), "r"(a[3]), "r"(b[0]), "r"(b[1]));
}
__device__ __forceinline__ void cpa16(uint32_t s, const void* g) {
    asm volatile("cp.async.cg.shared.global [%0], [%1], 16;\n" :: "r"(s), "l"(g));
}
__device__ __forceinline__ void cp_commit() {
    asm volatile("cp.async.commit_group;\n" ::: "memory");
}
template<int N>
__device__ __forceinline__ void cp_wait() {
    asm volatile("cp.async.wait_group %0;\n" :: "n"(N) : "memory");
}
__device__ __forceinline__ void ldm_x4(uint32_t& d0, uint32_t& d1, uint32_t& d2, uint32_t& d3,
                                       uint32_t addr) {
    asm volatile("ldmatrix.sync.aligned.m8n8.x4.shared.b16 {%0,%1,%2,%3},[%4];"
                 : "=r"(d0), "=r"(d1), "=r"(d2), "=r"(d3) : "r"(addr));
}
__device__ __forceinline__ void ldm_x4_t(uint32_t& d0, uint32_t& d1, uint32_t& d2, uint32_t& d3,
                                         uint32_t addr) {
    asm volatile("ldmatrix.sync.aligned.m8n8.x4.trans.shared.b16 {%0,%1,%2,%3},[%4];"
                 : "=r"(d0), "=r"(d1), "=r"(d2), "=r"(d3) : "r"(addr));
}
__device__ __forceinline__ uint32_t pack_h2(float a, float b) {
    __half2 h = __floats2half2_rn(a, b);
    return *reinterpret_cast<uint32_t*>(&h);
}

// ---------------- fp16 GEMM v5: TBK=64, 3-stage ring, persistent CTAs ----------------
// Tile variants: 128x256 (warp 64x64, 1 CTA/SM) and 128x64 (warp 32x32, 2 CTA/SM).
constexpr int GBW = 36;   // words per 64-half row (144B) -> ldmatrix conflict-free

template<int TBN_, int WM, int WN, bool OUTF, int MINB>
__global__ void __launch_bounds__(256, MINB)
tgemm_h5(const __half* __restrict__ A, const __half* __restrict__ B,
         void* __restrict__ Cout, int K, int lda, int ldb, int ldc,
         int tilesM, int tilesN)
{
    constexpr int MI = WM / 16;
    constexpr int NJ = WN / 8;
    constexpr int WARPS_M = 128 / WM;
    constexpr int STAGE_W = (128 + TBN_) * GBW;

    extern __shared__ uint32_t smem[];

    const int tid  = threadIdx.x;
    const int lane = tid & 31;
    const int warp = tid >> 5;
    const int wm0 = (warp % WARPS_M) * WM;
    const int wn0 = (warp / WARPS_M) * WN;
    const int lr = lane & 7, lm = lane >> 3;
    const int qr = lane >> 2, qc = lane & 3;

    const uint32_t sbase = (uint32_t)__cvta_generic_to_shared(smem);

    const int NT = K / 64;
    const int ntiles = tilesM * tilesN;

    for (int t = blockIdx.x; t < ntiles; t += gridDim.x) {
        const int m0 = (t / tilesN) * 128;
        const int n0 = (t % tilesN) * TBN_;

        auto issueTile = [&](int k0, int st) {
            const uint32_t abase = sbase + st * (STAGE_W * 4);
            const uint32_t bbase = abase + 128 * (GBW * 4);
#pragma unroll
            for (int n = 0; n < 4; n++) {          // A: 128 rows x 8 chunks = 1024
                int idx = tid + n * 256;
                int row = idx >> 3, c = idx & 7;
                cpa16(abase + row * (GBW * 4) + c * 16,
                      (const char*)A + ((size_t)(m0 + row) * lda + k0) * 2 + c * 16);
            }
#pragma unroll
            for (int n = 0; n < TBN_ / 32; n++) {  // B: TBN rows x 8 chunks
                int idx = tid + n * 256;
                int row = idx >> 3, c = idx & 7;
                cpa16(bbase + row * (GBW * 4) + c * 16,
                      (const char*)B + ((size_t)(n0 + row) * ldb + k0) * 2 + c * 16);
            }
            cp_commit();
        };

        float acc[MI][NJ][4];
#pragma unroll
        for (int i = 0; i < MI; i++)
#pragma unroll
            for (int j = 0; j < NJ; j++)
#pragma unroll
                for (int r = 0; r < 4; r++) acc[i][j][r] = 0.0f;

        issueTile(0, 0);
        issueTile(64, 1);

        for (int kt = 0; kt < NT; kt++) {
            if (kt == NT - 1) cp_wait<0>(); else cp_wait<1>();
            __syncthreads();
            if (kt + 2 < NT) issueTile((kt + 2) * 64, (kt + 2) % 3);

            const int st = kt % 3;
            const uint32_t abase = sbase + st * (STAGE_W * 4);
            const uint32_t bbase = abase + 128 * (GBW * 4);

#pragma unroll
            for (int s = 0; s < 4; s++) {          // 4 x k16 per stage
                uint32_t a[MI][4], b[NJ][2];
#pragma unroll
                for (int i = 0; i < MI; i++) {
                    uint32_t addr = abase +
                        (uint32_t)(wm0 + i * 16 + (lm & 1) * 8 + lr) * (GBW * 4) +
                        s * 32 + (lm >> 1) * 16;
                    ldm_x4(a[i][0], a[i][1], a[i][2], a[i][3], addr);
                }
#pragma unroll
                for (int p = 0; p < NJ / 2; p++) {
                    uint32_t addr = bbase +
                        (uint32_t)(wn0 + p * 16 + (lm >> 1) * 8 + lr) * (GBW * 4) +
                        s * 32 + (lm & 1) * 16;
                    ldm_x4(b[2 * p][0], b[2 * p][1], b[2 * p + 1][0], b[2 * p + 1][1], addr);
                }
#pragma unroll
                for (int i = 0; i < MI; i++)
#pragma unroll
                    for (int j = 0; j < NJ; j++)
                        mma_f16(acc[i][j], a[i], b[j]);
            }
        }

#pragma unroll
        for (int i = 0; i < MI; i++) {
#pragma unroll
            for (int j = 0; j < NJ; j++) {
                const int r = m0 + wm0 + i * 16 + qr;
                const int c = n0 + wn0 + j * 8 + 2 * qc;
                if (OUTF) {
                    float* C = (float*)Cout;
                    float2 v0 = { acc[i][j][0], acc[i][j][1] };
                    float2 v1 = { acc[i][j][2], acc[i][j][3] };
                    *reinterpret_cast<float2*>(&C[(size_t)r * ldc + c]) = v0;
                    *reinterpret_cast<float2*>(&C[(size_t)(r + 8) * ldc + c]) = v1;
                } else {
                    __half* C = (__half*)Cout;
                    *reinterpret_cast<__half2*>(&C[(size_t)r * ldc + c]) =
                        __floats2half2_rn(acc[i][j][0], acc[i][j][1]);
                    *reinterpret_cast<__half2*>(&C[(size_t)(r + 8) * ldc + c]) =
                        __floats2half2_rn(acc[i][j][2], acc[i][j][3]);
                }
            }
        }
        __syncthreads();   // protect stage buffers before next tile's prologue
    }
}

constexpr int SM5_G256 = (128 + 256) * GBW * 4 * 3;   // 165,888 B (1 CTA/SM)
constexpr int SM5_G64  = (128 + 64)  * GBW * 4 * 3;   //  82,944 B (2 CTA/SM)

// ---------------- fused flash attention v5 (R11/R12 winner, unchanged) ----------------
constexpr int FBR = 128;
constexpr int FBC = 64;
constexpr int FQW = 100;
constexpr int FW_Q = FBR * FQW;
constexpr int FW_KV = FBC * FQW;
constexpr int FSTG = 2 * FW_KV;
constexpr int FSMEM = (FW_Q + 3 * FSTG) * 4;     // 204,800 B

__global__ void __launch_bounds__(256, 1)
flash_attn_kernel(float scale)
{
    extern __shared__ uint32_t sh[];
    uint32_t* Qs = sh;

    const int mb = (int)gridDim.x - 1 - (int)blockIdx.x;
    const int bh = blockIdx.y;
    const int b = bh / cH, h = bh % cH;
    const int m0 = mb * FBR;
    const int tid = threadIdx.x;
    const int lane = tid & 31, warp = tid >> 5;
    const int wr = warp * 16;
    const int qr = lane >> 2, qc = lane & 3;
    const int lr = lane & 7, lm = lane >> 3;

    const char* Qb  = (const char*)g_qallh + ((size_t)b * cL * cNQ + (size_t)h * cDQK) * 2;
    const char* upK = (const char*)g_uph   + ((size_t)b * cL * cNUP + (size_t)h * 320) * 2;
    const char* kvK = (const char*)g_kvh   + ((size_t)b * cL * cNKV + cRK) * 2;

    const uint32_t qs_addr = (uint32_t)__cvta_generic_to_shared(Qs);
    const uint32_t st_addr = qs_addr + FW_Q * 4;

    auto prefetchKV = [&](int kb, int st) {
        const uint32_t kb_s = st_addr + st * (FSTG * 4);
        const uint32_t vb_s = kb_s + FW_KV * 4;
#pragma unroll
        for (int n = 0; n < 6; n++) {
            int idx = tid + n * 256;
            int r = idx / 24, c = idx % 24;
            const size_t key = (size_t)(kb * FBC + r);
            const char* ksrc = (c < 16)
                ? upK + key * (cNUP * 2) + c * 16
                : kvK + key * (cNKV * 2) + (c - 16) * 16;
            cpa16(kb_s + r * (FQW * 4) + c * 16, ksrc);
            cpa16(vb_s + r * (FQW * 4) + c * 16, upK + 256 + key * (cNUP * 2) + c * 16);
        }
        cp_commit();
    };

    const int kbmax = 2 * mb + 1;

    prefetchKV(0, 0);
    for (int n = 0; n < 12; n++) {
        int idx = tid + n * 256;
        int r = idx / 24, c = idx % 24;
        uint4 v = *reinterpret_cast<const uint4*>(Qb + (size_t)(m0 + r) * (cNQ * 2) + c * 16);
        *reinterpret_cast<uint4*>((char*)Qs + r * (FQW * 4) + c * 16) = v;
    }
    if (1 <= kbmax) prefetchKV(1, 1);
    __syncthreads();

    uint32_t qa[12][4];
#pragma unroll
    for (int ks = 0; ks < 12; ks++) {
        uint32_t addr = qs_addr +
            (uint32_t)(wr + (lm & 1) * 8 + lr) * (FQW * 4) +
            ks * 32 + (lm >> 1) * 16;
        ldm_x4(qa[ks][0], qa[ks][1], qa[ks][2], qa[ks][3], addr);
    }

    float oacc[24][4];
#pragma unroll
    for (int j = 0; j < 24; j++)
#pragma unroll
        for (int e = 0; e < 4; e++) oacc[j][e] = 0.0f;
    float mrow[2] = { -1e30f, -1e30f };
    float lrow[2] = { 0.0f, 0.0f };

    const int rowg0 = m0 + wr + qr;
    for (int kb = 0; kb <= kbmax; kb++) {
        if (kb < kbmax) cp_wait<1>(); else cp_wait<0>();
        __syncthreads();
        if (kb + 2 <= kbmax) prefetchKV(kb + 2, (kb + 2) % 3);

        const bool skip = (kb * FBC > m0 + wr + 15);
        if (!skip) {
            const uint32_t kbuf = st_addr + (kb % 3) * (FSTG * 4);
            const uint32_t vbuf = kbuf + FW_KV * 4;

            float sacc[8][4];
#pragma unroll
            for (int j = 0; j < 8; j++)
#pragma unroll
                for (int e = 0; e < 4; e++) sacc[j][e] = 0.0f;

#pragma unroll
            for (int ks = 0; ks < 12; ks++) {
#pragma unroll
                for (int p = 0; p < 4; p++) {
                    uint32_t b2[4];
                    uint32_t addr = kbuf +
                        (uint32_t)(p * 16 + (lm >> 1) * 8 + lr) * (FQW * 4) +
                        ks * 32 + (lm & 1) * 16;
                    ldm_x4(b2[0], b2[1], b2[2], b2[3], addr);
                    uint32_t b0[2] = { b2[0], b2[1] };
                    uint32_t b1[2] = { b2[2], b2[3] };
                    mma_f16(sacc[2 * p], qa[ks], b0);
                    mma_f16(sacc[2 * p + 1], qa[ks], b1);
                }
            }

            const bool diag = (kb * FBC + FBC - 1 > m0 + wr);
            float tmax[2] = { -1e30f, -1e30f };
#pragma unroll
            for (int j = 0; j < 8; j++) {
#pragma unroll
                for (int e = 0; e < 4; e++) {
                    float s = sacc[j][e] * scale;
                    if (diag) {
                        int col = kb * FBC + j * 8 + 2 * qc + (e & 1);
                        int row = rowg0 + 8 * (e >> 1);
                        if (col > row) s = -1e30f;
                    }
                    sacc[j][e] = s;
                    tmax[e >> 1] = fmaxf(tmax[e >> 1], s);
                }
            }
#pragma unroll
            for (int half = 0; half < 2; half++) {
                tmax[half] = fmaxf(tmax[half], __shfl_xor_sync(0xffffffffu, tmax[half], 1));
                tmax[half] = fmaxf(tmax[half], __shfl_xor_sync(0xffffffffu, tmax[half], 2));
            }

            float mnew[2], alf[2], psum[2] = { 0.0f, 0.0f };
#pragma unroll
            for (int half = 0; half < 2; half++) {
                mnew[half] = fmaxf(mrow[half], tmax[half]);
                alf[half] = __expf(mrow[half] - mnew[half]);
                mrow[half] = mnew[half];
            }

#pragma unroll
            for (int j = 0; j < 8; j++) {
                sacc[j][0] = __expf(sacc[j][0] - mnew[0]);
                sacc[j][1] = __expf(sacc[j][1] - mnew[0]);
                sacc[j][2] = __expf(sacc[j][2] - mnew[1]);
                sacc[j][3] = __expf(sacc[j][3] - mnew[1]);
                psum[0] += sacc[j][0] + sacc[j][1];
                psum[1] += sacc[j][2] + sacc[j][3];
            }
#pragma unroll
            for (int half = 0; half < 2; half++) {
                psum[half] += __shfl_xor_sync(0xffffffffu, psum[half], 1);
                psum[half] += __shfl_xor_sync(0xffffffffu, psum[half], 2);
                lrow[half] = lrow[half] * alf[half] + psum[half];
            }

#pragma unroll
            for (int j = 0; j < 24; j++) {
                oacc[j][0] *= alf[0];
                oacc[j][1] *= alf[0];
                oacc[j][2] *= alf[1];
                oacc[j][3] *= alf[1];
            }

            const int g = lane >> 3, lj = lane & 7;
            const uint32_t vrow_base = vbuf + ((g & 1) * 8 + lj) * (FQW * 4) + (g >> 1) * 16;
#pragma unroll
            for (int ks2 = 0; ks2 < 4; ks2++) {
                uint32_t pa[4] = {
                    pack_h2(sacc[2 * ks2][0],     sacc[2 * ks2][1]),
                    pack_h2(sacc[2 * ks2][2],     sacc[2 * ks2][3]),
                    pack_h2(sacc[2 * ks2 + 1][0], sacc[2 * ks2 + 1][1]),
                    pack_h2(sacc[2 * ks2 + 1][2], sacc[2 * ks2 + 1][3])
                };
                const uint32_t krow = vrow_base + ks2 * 16 * (FQW * 4);
#pragma unroll
                for (int jp = 0; jp < 12; jp++) {
                    uint32_t d0, d1, d2, d3;
                    ldm_x4_t(d0, d1, d2, d3, krow + jp * 32);
                    uint32_t b0[2] = { d0, d1 };
                    uint32_t b1[2] = { d2, d3 };
                    mma_f16(oacc[2 * jp], pa, b0);
                    mma_f16(oacc[2 * jp + 1], pa, b1);
                }
            }
        }
    }

    const float inv0 = 1.0f / lrow[0];
    const float inv1 = 1.0f / lrow[1];
    const size_t base0 = ((size_t)b * cL + (m0 + wr + qr)) * cNQ + (size_t)h * cDQK;
    const size_t base1 = base0 + 8 * cNQ;
#pragma unroll
    for (int j = 0; j < 24; j++) {
        const int c = j * 8 + 2 * qc;
        *reinterpret_cast<__half2*>(&g_AOh[base0 + c]) =
            __floats2half2_rn(oacc[j][0] * inv0, oacc[j][1] * inv0);
        *reinterpret_cast<__half2*>(&g_AOh[base1 + c]) =
            __floats2half2_rn(oacc[j][2] * inv1, oacc[j][3] * inv1);
    }
}

// ---------------- prep kernels ----------------
__global__ void f2h_kernel(const float* __restrict__ s, __half* __restrict__ d, size_t n)
{
    size_t i = ((size_t)blockIdx.x * blockDim.x + threadIdx.x) * 8;
    if (i >= n) return;
    float4 a = *reinterpret_cast<const float4*>(&s[i]);
    float4 b = *reinterpret_cast<const float4*>(&s[i + 4]);
    __half2 h[4] = { __floats2half2_rn(a.x, a.y), __floats2half2_rn(a.z, a.w),
                     __floats2half2_rn(b.x, b.y), __floats2half2_rn(b.z, b.w) };
    *reinterpret_cast<uint4*>(&d[i]) = *reinterpret_cast<uint4*>(h);
}

__global__ void transpose_h_kernel(const float* __restrict__ src, __half* __restrict__ dst,
                                   int R, int C)
{
    __shared__ float t[32][65];
    const int c0 = blockIdx.x * 32, r0 = blockIdx.y * 64;
    const int x = threadIdx.x, y = threadIdx.y;   // 32 x 8
#pragma unroll
    for (int ry = 0; ry < 64; ry += 8)
        t[x][ry + y] = src[(size_t)(r0 + ry + y) * C + c0 + x];
    __syncthreads();
    const int tid = y * 32 + x;
    const int drow = tid >> 3;
    const int seg  = (tid & 7) * 8;
    __half2 h[4];
#pragma unroll
    for (int k = 0; k < 4; k++)
        h[k] = __floats2half2_rn(t[drow][seg + 2 * k], t[drow][seg + 2 * k + 1]);
    *reinterpret_cast<uint4*>(&dst[(size_t)(c0 + drow) * R + r0 + seg]) =
        *reinterpret_cast<uint4*>(h);
}

// ---------------- RoPE (in-place on half) ----------------
__global__ void rope_q_kernel(const float* __restrict__ cosT, const float* __restrict__ sinT)
{
    int idx = blockIdx.x * blockDim.x + threadIdx.x;
    if (idx >= cM * cH * (cRD / 2)) return;
    int i = idx % (cRD / 2);
    int h = (idx / (cRD / 2)) % cH;
    int row = idx / ((cRD / 2) * cH);
    int l = row % cL;
    float c = cosT[l * (cRD / 2) + i];
    float s = sinT[l * (cRD / 2) + i];
    __half2* p = reinterpret_cast<__half2*>(&g_qallh[(size_t)row * cNQ + h * cDQK + cDH + 2 * i]);
    float2 v = __half22float2(*p);
    *p = __floats2half2_rn(v.x * c - v.y * s, v.x * s + v.y * c);
}

__global__ void rope_k_kernel(const float* __restrict__ cosT, const float* __restrict__ sinT)
{
    int idx = blockIdx.x * blockDim.x + threadIdx.x;
    if (idx >= cM * (cRD / 2)) return;
    int i = idx % (cRD / 2);
    int row = idx / (cRD / 2);
    int l = row % cL;
    float c = cosT[l * (cRD / 2) + i];
    float s = sinT[l * (cRD / 2) + i];
    __half2* p = reinterpret_cast<__half2*>(&g_kvh[(size_t)row * cNKV + cRK + 2 * i]);
    float2 v = __half22float2(*p);
    *p = __floats2half2_rn(v.x * c - v.y * s, v.x * s + v.y * c);
}

// ---------------- launch ----------------
extern "C" void kernel_launch(void* const* d_in, const int* in_sizes, int n_in,
                              void* d_out, int out_size)
{
    const float* x    = (const float*)d_in[0];
    const float* cosT = (const float*)d_in[1];
    const float* sinT = (const float*)d_in[2];
    const float* wq   = (const float*)d_in[3];
    const float* wkvd = (const float*)d_in[4];
    const float* wup  = (const float*)d_in[5];
    const float* wout = (const float*)d_in[6];
    float* out = (float*)d_out;

    __half *p_xh, *p_wqT, *p_wkvT, *p_wupT, *p_woT;
    __half *p_qall, *p_kv, *p_up, *p_ao;
    cudaGetSymbolAddress((void**)&p_xh,   g_xh);
    cudaGetSymbolAddress((void**)&p_wqT,  g_wqT);
    cudaGetSymbolAddress((void**)&p_wkvT, g_wkvT);
    cudaGetSymbolAddress((void**)&p_wupT, g_wupT);
    cudaGetSymbolAddress((void**)&p_woT,  g_woT);
    cudaGetSymbolAddress((void**)&p_qall, g_qallh);
    cudaGetSymbolAddress((void**)&p_kv,   g_kvh);
    cudaGetSymbolAddress((void**)&p_up,   g_uph);
    cudaGetSymbolAddress((void**)&p_ao,   g_AOh);

    cudaFuncSetAttribute(flash_attn_kernel,
                         cudaFuncAttributeMaxDynamicSharedMemorySize, FSMEM);
    cudaFuncSetAttribute((const void*)tgemm_h5<256, 64, 64, false, 1>,
                         cudaFuncAttributeMaxDynamicSharedMemorySize, SM5_G256);
    cudaFuncSetAttribute((const void*)tgemm_h5<64, 32, 32, false, 2>,
                         cudaFuncAttributeMaxDynamicSharedMemorySize, SM5_G64);
    cudaFuncSetAttribute((const void*)tgemm_h5<256, 64, 64, true, 1>,
                         cudaFuncAttributeMaxDynamicSharedMemorySize, SM5_G256);

    const float scale = 1.0f / sqrtf((float)cDQK);
    dim3 tblk(32, 8);

    // (1) x -> half
    f2h_kernel<<<(unsigned)(((size_t)cM * cE / 8 + 255) / 256), 256>>>(x, p_xh, (size_t)cM * cE);
    // (2)(3) transposes needed by wq / kv
    transpose_h_kernel<<<dim3(cNQ / 32, cE / 64), tblk>>>(wq, p_wqT, cE, cNQ);
    transpose_h_kernel<<<dim3(cNKV / 32, cE / 64), tblk>>>(wkvd, p_wkvT, cE, cNKV);
    // (4) q_all = x @ wq  (tiles 32 x 12) — ncu capture lands here
    tgemm_h5<256, 64, 64, false, 1><<<148, 256, SM5_G256>>>(
        p_xh, p_wqT, p_qall, cE, cE, cE, cNQ, cM / 128, cNQ / 256);
    // (5) kv_lat = x @ wkv_down  (tiles 32 x 9)
    tgemm_h5<64, 32, 32, false, 2><<<296, 256, SM5_G64>>>(
        p_xh, p_wkvT, p_kv, cE, cE, cE, cNKV, cM / 128, cNKV / 64);
    // (6) wup transpose, (7) up = c_kv @ w_up  (tiles 32 x 20)
    transpose_h_kernel<<<dim3(cNUP / 32, cRK / 64), tblk>>>(wup, p_wupT, cRK, cNUP);
    tgemm_h5<256, 64, 64, false, 1><<<148, 256, SM5_G256>>>(
        p_kv, p_wupT, p_up, cRK, cNKV, cRK, cNUP, cM / 128, cNUP / 256);
    // (8) wout transpose
    transpose_h_kernel<<<dim3(cE / 32, cNQ / 64), tblk>>>(wout, p_woT, cNQ, cE);
    // (9)(10) RoPE in place
    rope_q_kernel<<<(cM * cH * (cRD / 2) + 255) / 256, 256>>>(cosT, sinT);
    rope_k_kernel<<<(cM * (cRD / 2) + 255) / 256, 256>>>(cosT, sinT);
    // (11) fused flash attention (direct producer reads)
    flash_attn_kernel<<<dim3(cL / FBR, cBH), 256, FSMEM>>>(scale);
    // (12) out = AO @ w_out (fp32 output, tiles 32 x 8)
    tgemm_h5<256, 64, 64, true, 1><<<148, 256, SM5_G256>>>(
        p_ao, p_woT, out, cNQ, cNQ, cNQ, cE, cM / 128, cE / 256);
}

// round 14
// speedup vs baseline: 1.0804x; 1.0804x over previous
#include <cuda_runtime.h>
#include <cuda_fp16.h>
#include <math.h>
#include <stdint.h>

// ---------------- problem constants ----------------
constexpr int cH   = 16;
constexpr int cDH  = 128;
constexpr int cRK  = 512;
constexpr int cRD  = 64;
constexpr int cB   = 2;
constexpr int cL   = 2048;
constexpr int cE   = 2048;
constexpr int cDQK = cDH + cRD;          // 192
constexpr int cNQ  = cH * cDQK;          // 3072
constexpr int cNKV = cRK + cRD;          // 576
constexpr int cNUP = cH * (2*cDH + cRD); // 5120 (per-head block of 320)
constexpr int cM   = cB * cL;            // 4096
constexpr int cBH  = cB * cH;            // 32
constexpr int PGRID = 296;               // persistent grid (2 per SM x 148)

// ---------------- scratch (half everywhere) ----------------
__device__ __half g_xh   [(size_t)cM * cE];
__device__ __half g_wqT  [(size_t)cNQ * cE];
__device__ __half g_wkvT [(size_t)cNKV * cE];
__device__ __half g_wupT [(size_t)cNUP * cRK];
__device__ __half g_woT  [(size_t)cE * cNQ];
__device__ __half g_qallh[(size_t)cM * cNQ];
__device__ __half g_kvh  [(size_t)cM * cNKV];
__device__ __half g_uph  [(size_t)cM * cNUP];
__device__ __half g_AOh  [(size_t)cM * cNQ];

// ---------------- low-level helpers ----------------
__device__ __forceinline__ void mma_f16(float* d, const uint32_t* a, const uint32_t* b) {
    asm volatile(
        "mma.sync.aligned.m16n8k16.row.col.f32.f16.f16.f32 "
        "{%0,%1,%2,%3},{%4,%5,%6,%7},{%8,%9},{%0,%1,%2,%3};"
        : "+f"(d[0]), "+f"(d[1]), "+f"(d[2]), "+f"(d[3])
        : "r"(a[0]), "r"(a[1]), "r"(a[2]), "r"(a[3]), "r"(b[0]), "r"(b[1]));
}
__device__ __forceinline__ void cpa16(uint32_t s, const void* g) {
    asm volatile("cp.async.cg.shared.global [%0], [%1], 16;\n" :: "r"(s), "l"(g));
}
__device__ __forceinline__ void cp_commit() {
    asm volatile("cp.async.commit_group;\n" ::: "memory");
}
template<int N>
__device__ __forceinline__ void cp_wait() {
    asm volatile("cp.async.wait_group %0;\n" :: "n"(N) : "memory");
}
__device__ __forceinline__ void ldm_x4(uint32_t& d0, uint32_t& d1, uint32_t& d2, uint32_t& d3,
                                       uint32_t addr) {
    asm volatile("ldmatrix.sync.aligned.m8n8.x4.shared.b16 {%0,%1,%2,%3},[%4];"
                 : "=r"(d0), "=r"(d1), "=r"(d2), "=r"(d3) : "r"(addr));
}
__device__ __forceinline__ void ldm_x4_t(uint32_t& d0, uint32_t& d1, uint32_t& d2, uint32_t& d3,
                                         uint32_t addr) {
    asm volatile("ldmatrix.sync.aligned.m8n8.x4.trans.shared.b16 {%0,%1,%2,%3},[%4];"
                 : "=r"(d0), "=r"(d1), "=r"(d2), "=r"(d3) : "r"(addr));
}
__device__ __forceinline__ uint32_t pack_h2(float a, float b) {
    __half2 h = __floats2half2_rn(a, b);
    return *reinterpret_cast<uint32_t*>(&h);
}

// ---------------- fp16 GEMM v4 (R12 winner): TBK=64, 3-stage ring, persistent ----------------
constexpr int GBW = 36;   // words per 64-half row (144B) -> ldmatrix conflict-free

template<int TBN_, int WM, int WN, bool OUTF>
__global__ void __launch_bounds__(256, 2)
tgemm_h4(const __half* __restrict__ A, const __half* __restrict__ B,
         void* __restrict__ Cout, int K, int lda, int ldb, int ldc,
         int tilesM, int tilesN)
{
    constexpr int MI = WM / 16;
    constexpr int NJ = WN / 8;
    constexpr int WARPS_M = 128 / WM;
    constexpr int STAGE_W = (128 + TBN_) * GBW;

    extern __shared__ uint32_t smem[];

    const int tid  = threadIdx.x;
    const int lane = tid & 31;
    const int warp = tid >> 5;
    const int wm0 = (warp % WARPS_M) * WM;
    const int wn0 = (warp / WARPS_M) * WN;
    const int lr = lane & 7, lm = lane >> 3;
    const int qr = lane >> 2, qc = lane & 3;

    const uint32_t sbase = (uint32_t)__cvta_generic_to_shared(smem);

    const int NT = K / 64;
    const int ntiles = tilesM * tilesN;

    for (int t = blockIdx.x; t < ntiles; t += gridDim.x) {
        const int m0 = (t / tilesN) * 128;
        const int n0 = (t % tilesN) * TBN_;

        auto issueTile = [&](int k0, int st) {
            const uint32_t abase = sbase + st * (STAGE_W * 4);
            const uint32_t bbase = abase + 128 * (GBW * 4);
#pragma unroll
            for (int n = 0; n < 4; n++) {          // A: 128 rows x 8 chunks
                int idx = tid + n * 256;
                int row = idx >> 3, c = idx & 7;
                cpa16(abase + row * (GBW * 4) + c * 16,
                      (const char*)A + ((size_t)(m0 + row) * lda + k0) * 2 + c * 16);
            }
#pragma unroll
            for (int n = 0; n < TBN_ / 32; n++) {  // B: TBN rows x 8 chunks
                int idx = tid + n * 256;
                int row = idx >> 3, c = idx & 7;
                cpa16(bbase + row * (GBW * 4) + c * 16,
                      (const char*)B + ((size_t)(n0 + row) * ldb + k0) * 2 + c * 16);
            }
            cp_commit();
        };

        float acc[MI][NJ][4];
#pragma unroll
        for (int i = 0; i < MI; i++)
#pragma unroll
            for (int j = 0; j < NJ; j++)
#pragma unroll
                for (int r = 0; r < 4; r++) acc[i][j][r] = 0.0f;

        issueTile(0, 0);
        issueTile(64, 1);

        for (int kt = 0; kt < NT; kt++) {
            if (kt == NT - 1) cp_wait<0>(); else cp_wait<1>();
            __syncthreads();
            if (kt + 2 < NT) issueTile((kt + 2) * 64, (kt + 2) % 3);

            const int st = kt % 3;
            const uint32_t abase = sbase + st * (STAGE_W * 4);
            const uint32_t bbase = abase + 128 * (GBW * 4);

#pragma unroll
            for (int s = 0; s < 4; s++) {          // 4 x k16 per stage
                uint32_t a[MI][4], b[NJ][2];
#pragma unroll
                for (int i = 0; i < MI; i++) {
                    uint32_t addr = abase +
                        (uint32_t)(wm0 + i * 16 + (lm & 1) * 8 + lr) * (GBW * 4) +
                        s * 32 + (lm >> 1) * 16;
                    ldm_x4(a[i][0], a[i][1], a[i][2], a[i][3], addr);
                }
#pragma unroll
                for (int p = 0; p < NJ / 2; p++) {
                    uint32_t addr = bbase +
                        (uint32_t)(wn0 + p * 16 + (lm >> 1) * 8 + lr) * (GBW * 4) +
                        s * 32 + (lm & 1) * 16;
                    ldm_x4(b[2 * p][0], b[2 * p][1], b[2 * p + 1][0], b[2 * p + 1][1], addr);
                }
#pragma unroll
                for (int i = 0; i < MI; i++)
#pragma unroll
                    for (int j = 0; j < NJ; j++)
                        mma_f16(acc[i][j], a[i], b[j]);
            }
        }

#pragma unroll
        for (int i = 0; i < MI; i++) {
#pragma unroll
            for (int j = 0; j < NJ; j++) {
                const int r = m0 + wm0 + i * 16 + qr;
                const int c = n0 + wn0 + j * 8 + 2 * qc;
                if (OUTF) {
                    float* C = (float*)Cout;
                    float2 v0 = { acc[i][j][0], acc[i][j][1] };
                    float2 v1 = { acc[i][j][2], acc[i][j][3] };
                    *reinterpret_cast<float2*>(&C[(size_t)r * ldc + c]) = v0;
                    *reinterpret_cast<float2*>(&C[(size_t)(r + 8) * ldc + c]) = v1;
                } else {
                    __half* C = (__half*)Cout;
                    *reinterpret_cast<__half2*>(&C[(size_t)r * ldc + c]) =
                        __floats2half2_rn(acc[i][j][0], acc[i][j][1]);
                    *reinterpret_cast<__half2*>(&C[(size_t)(r + 8) * ldc + c]) =
                        __floats2half2_rn(acc[i][j][2], acc[i][j][3]);
                }
            }
        }
        __syncthreads();
    }
}

constexpr int SM4_G128 = (128 + 128) * GBW * 4 * 3;   // 110,592 B
constexpr int SM4_G64  = (128 + 64)  * GBW * 4 * 3;   //  82,944 B

// ---------------- fused flash attention v5 (unchanged) ----------------
constexpr int FBR = 128;
constexpr int FBC = 64;
constexpr int FQW = 100;
constexpr int FW_Q = FBR * FQW;
constexpr int FW_KV = FBC * FQW;
constexpr int FSTG = 2 * FW_KV;
constexpr int FSMEM = (FW_Q + 3 * FSTG) * 4;     // 204,800 B

__global__ void __launch_bounds__(256, 1)
flash_attn_kernel(float scale)
{
    extern __shared__ uint32_t sh[];
    uint32_t* Qs = sh;

    const int mb = (int)gridDim.x - 1 - (int)blockIdx.x;
    const int bh = blockIdx.y;
    const int b = bh / cH, h = bh % cH;
    const int m0 = mb * FBR;
    const int tid = threadIdx.x;
    const int lane = tid & 31, warp = tid >> 5;
    const int wr = warp * 16;
    const int qr = lane >> 2, qc = lane & 3;
    const int lr = lane & 7, lm = lane >> 3;

    const char* Qb  = (const char*)g_qallh + ((size_t)b * cL * cNQ + (size_t)h * cDQK) * 2;
    const char* upK = (const char*)g_uph   + ((size_t)b * cL * cNUP + (size_t)h * 320) * 2;
    const char* kvK = (const char*)g_kvh   + ((size_t)b * cL * cNKV + cRK) * 2;

    const uint32_t qs_addr = (uint32_t)__cvta_generic_to_shared(Qs);
    const uint32_t st_addr = qs_addr + FW_Q * 4;

    auto prefetchKV = [&](int kb, int st) {
        const uint32_t kb_s = st_addr + st * (FSTG * 4);
        const uint32_t vb_s = kb_s + FW_KV * 4;
#pragma unroll
        for (int n = 0; n < 6; n++) {
            int idx = tid + n * 256;
            int r = idx / 24, c = idx % 24;
            const size_t key = (size_t)(kb * FBC + r);
            const char* ksrc = (c < 16)
                ? upK + key * (cNUP * 2) + c * 16
                : kvK + key * (cNKV * 2) + (c - 16) * 16;
            cpa16(kb_s + r * (FQW * 4) + c * 16, ksrc);
            cpa16(vb_s + r * (FQW * 4) + c * 16, upK + 256 + key * (cNUP * 2) + c * 16);
        }
        cp_commit();
    };

    const int kbmax = 2 * mb + 1;

    prefetchKV(0, 0);
    for (int n = 0; n < 12; n++) {
        int idx = tid + n * 256;
        int r = idx / 24, c = idx % 24;
        uint4 v = *reinterpret_cast<const uint4*>(Qb + (size_t)(m0 + r) * (cNQ * 2) + c * 16);
        *reinterpret_cast<uint4*>((char*)Qs + r * (FQW * 4) + c * 16) = v;
    }
    if (1 <= kbmax) prefetchKV(1, 1);
    __syncthreads();

    uint32_t qa[12][4];
#pragma unroll
    for (int ks = 0; ks < 12; ks++) {
        uint32_t addr = qs_addr +
            (uint32_t)(wr + (lm & 1) * 8 + lr) * (FQW * 4) +
            ks * 32 + (lm >> 1) * 16;
        ldm_x4(qa[ks][0], qa[ks][1], qa[ks][2], qa[ks][3], addr);
    }

    float oacc[24][4];
#pragma unroll
    for (int j = 0; j < 24; j++)
#pragma unroll
        for (int e = 0; e < 4; e++) oacc[j][e] = 0.0f;
    float mrow[2] = { -1e30f, -1e30f };
    float lrow[2] = { 0.0f, 0.0f };

    const int rowg0 = m0 + wr + qr;
    for (int kb = 0; kb <= kbmax; kb++) {
        if (kb < kbmax) cp_wait<1>(); else cp_wait<0>();
        __syncthreads();
        if (kb + 2 <= kbmax) prefetchKV(kb + 2, (kb + 2) % 3);

        const bool skip = (kb * FBC > m0 + wr + 15);
        if (!skip) {
            const uint32_t kbuf = st_addr + (kb % 3) * (FSTG * 4);
            const uint32_t vbuf = kbuf + FW_KV * 4;

            float sacc[8][4];
#pragma unroll
            for (int j = 0; j < 8; j++)
#pragma unroll
                for (int e = 0; e < 4; e++) sacc[j][e] = 0.0f;

#pragma unroll
            for (int ks = 0; ks < 12; ks++) {
#pragma unroll
                for (int p = 0; p < 4; p++) {
                    uint32_t b2[4];
                    uint32_t addr = kbuf +
                        (uint32_t)(p * 16 + (lm >> 1) * 8 + lr) * (FQW * 4) +
                        ks * 32 + (lm & 1) * 16;
                    ldm_x4(b2[0], b2[1], b2[2], b2[3], addr);
                    uint32_t b0[2] = { b2[0], b2[1] };
                    uint32_t b1[2] = { b2[2], b2[3] };
                    mma_f16(sacc[2 * p], qa[ks], b0);
                    mma_f16(sacc[2 * p + 1], qa[ks], b1);
                }
            }

            const bool diag = (kb * FBC + FBC - 1 > m0 + wr);
            float tmax[2] = { -1e30f, -1e30f };
#pragma unroll
            for (int j = 0; j < 8; j++) {
#pragma unroll
                for (int e = 0; e < 4; e++) {
                    float s = sacc[j][e] * scale;
                    if (diag) {
                        int col = kb * FBC + j * 8 + 2 * qc + (e & 1);
                        int row = rowg0 + 8 * (e >> 1);
                        if (col > row) s = -1e30f;
                    }
                    sacc[j][e] = s;
                    tmax[e >> 1] = fmaxf(tmax[e >> 1], s);
                }
            }
#pragma unroll
            for (int half = 0; half < 2; half++) {
                tmax[half] = fmaxf(tmax[half], __shfl_xor_sync(0xffffffffu, tmax[half], 1));
                tmax[half] = fmaxf(tmax[half], __shfl_xor_sync(0xffffffffu, tmax[half], 2));
            }

            float mnew[2], alf[2], psum[2] = { 0.0f, 0.0f };
#pragma unroll
            for (int half = 0; half < 2; half++) {
                mnew[half] = fmaxf(mrow[half], tmax[half]);
                alf[half] = __expf(mrow[half] - mnew[half]);
                mrow[half] = mnew[half];
            }

#pragma unroll
            for (int j = 0; j < 8; j++) {
                sacc[j][0] = __expf(sacc[j][0] - mnew[0]);
                sacc[j][1] = __expf(sacc[j][1] - mnew[0]);
                sacc[j][2] = __expf(sacc[j][2] - mnew[1]);
                sacc[j][3] = __expf(sacc[j][3] - mnew[1]);
                psum[0] += sacc[j][0] + sacc[j][1];
                psum[1] += sacc[j][2] + sacc[j][3];
            }
#pragma unroll
            for (int half = 0; half < 2; half++) {
                psum[half] += __shfl_xor_sync(0xffffffffu, psum[half], 1);
                psum[half] += __shfl_xor_sync(0xffffffffu, psum[half], 2);
                lrow[half] = lrow[half] * alf[half] + psum[half];
            }

#pragma unroll
            for (int j = 0; j < 24; j++) {
                oacc[j][0] *= alf[0];
                oacc[j][1] *= alf[0];
                oacc[j][2] *= alf[1];
                oacc[j][3] *= alf[1];
            }

            const int g = lane >> 3, lj = lane & 7;
            const uint32_t vrow_base = vbuf + ((g & 1) * 8 + lj) * (FQW * 4) + (g >> 1) * 16;
#pragma unroll
            for (int ks2 = 0; ks2 < 4; ks2++) {
                uint32_t pa[4] = {
                    pack_h2(sacc[2 * ks2][0],     sacc[2 * ks2][1]),
                    pack_h2(sacc[2 * ks2][2],     sacc[2 * ks2][3]),
                    pack_h2(sacc[2 * ks2 + 1][0], sacc[2 * ks2 + 1][1]),
                    pack_h2(sacc[2 * ks2 + 1][2], sacc[2 * ks2 + 1][3])
                };
                const uint32_t krow = vrow_base + ks2 * 16 * (FQW * 4);
#pragma unroll
                for (int jp = 0; jp < 12; jp++) {
                    uint32_t d0, d1, d2, d3;
                    ldm_x4_t(d0, d1, d2, d3, krow + jp * 32);
                    uint32_t b0[2] = { d0, d1 };
                    uint32_t b1[2] = { d2, d3 };
                    mma_f16(oacc[2 * jp], pa, b0);
                    mma_f16(oacc[2 * jp + 1], pa, b1);
                }
            }
        }
    }

    const float inv0 = 1.0f / lrow[0];
    const float inv1 = 1.0f / lrow[1];
    const size_t base0 = ((size_t)b * cL + (m0 + wr + qr)) * cNQ + (size_t)h * cDQK;
    const size_t base1 = base0 + 8 * cNQ;
#pragma unroll
    for (int j = 0; j < 24; j++) {
        const int c = j * 8 + 2 * qc;
        *reinterpret_cast<__half2*>(&g_AOh[base0 + c]) =
            __floats2half2_rn(oacc[j][0] * inv0, oacc[j][1] * inv0);
        *reinterpret_cast<__half2*>(&g_AOh[base1 + c]) =
            __floats2half2_rn(oacc[j][2] * inv1, oacc[j][3] * inv1);
    }
}

// ---------------- prep kernels ----------------
__global__ void f2h_kernel(const float* __restrict__ s, __half* __restrict__ d, size_t n)
{
    size_t i = ((size_t)blockIdx.x * blockDim.x + threadIdx.x) * 8;
    if (i >= n) return;
    float4 a = *reinterpret_cast<const float4*>(&s[i]);
    float4 b = *reinterpret_cast<const float4*>(&s[i + 4]);
    __half2 h[4] = { __floats2half2_rn(a.x, a.y), __floats2half2_rn(a.z, a.w),
                     __floats2half2_rn(b.x, b.y), __floats2half2_rn(b.z, b.w) };
    *reinterpret_cast<uint4*>(&d[i]) = *reinterpret_cast<uint4*>(h);
}

__global__ void transpose_h_kernel(const float* __restrict__ src, __half* __restrict__ dst,
                                   int R, int C)
{
    __shared__ float t[32][65];
    const int c0 = blockIdx.x * 32, r0 = blockIdx.y * 64;
    const int x = threadIdx.x, y = threadIdx.y;   // 32 x 8
#pragma unroll
    for (int ry = 0; ry < 64; ry += 8)
        t[x][ry + y] = src[(size_t)(r0 + ry + y) * C + c0 + x];
    __syncthreads();
    const int tid = y * 32 + x;
    const int drow = tid >> 3;
    const int seg  = (tid & 7) * 8;
    __half2 h[4];
#pragma unroll
    for (int k = 0; k < 4; k++)
        h[k] = __floats2half2_rn(t[drow][seg + 2 * k], t[drow][seg + 2 * k + 1]);
    *reinterpret_cast<uint4*>(&dst[(size_t)(c0 + drow) * R + r0 + seg]) =
        *reinterpret_cast<uint4*>(h);
}

// ---------------- RoPE (in-place on half) ----------------
__global__ void rope_q_kernel(const float* __restrict__ cosT, const float* __restrict__ sinT)
{
    int idx = blockIdx.x * blockDim.x + threadIdx.x;
    if (idx >= cM * cH * (cRD / 2)) return;
    int i = idx % (cRD / 2);
    int h = (idx / (cRD / 2)) % cH;
    int row = idx / ((cRD / 2) * cH);
    int l = row % cL;
    float c = cosT[l * (cRD / 2) + i];
    float s = sinT[l * (cRD / 2) + i];
    __half2* p = reinterpret_cast<__half2*>(&g_qallh[(size_t)row * cNQ + h * cDQK + cDH + 2 * i]);
    float2 v = __half22float2(*p);
    *p = __floats2half2_rn(v.x * c - v.y * s, v.x * s + v.y * c);
}

__global__ void rope_k_kernel(const float* __restrict__ cosT, const float* __restrict__ sinT)
{
    int idx = blockIdx.x * blockDim.x + threadIdx.x;
    if (idx >= cM * (cRD / 2)) return;
    int i = idx % (cRD / 2);
    int row = idx / (cRD / 2);
    int l = row % cL;
    float c = cosT[l * (cRD / 2) + i];
    float s = sinT[l * (cRD / 2) + i];
    __half2* p = reinterpret_cast<__half2*>(&g_kvh[(size_t)row * cNKV + cRK + 2 * i]);
    float2 v = __half22float2(*p);
    *p = __floats2half2_rn(v.x * c - v.y * s, v.x * s + v.y * c);
}

// ---------------- launch (fork-join multi-stream, graph-capturable) ----------------
extern "C" void kernel_launch(void* const* d_in, const int* in_sizes, int n_in,
                              void* d_out, int out_size)
{
    const float* x    = (const float*)d_in[0];
    const float* cosT = (const float*)d_in[1];
    const float* sinT = (const float*)d_in[2];
    const float* wq   = (const float*)d_in[3];
    const float* wkvd = (const float*)d_in[4];
    const float* wup  = (const float*)d_in[5];
    const float* wout = (const float*)d_in[6];
    float* out = (float*)d_out;

    __half *p_xh, *p_wqT, *p_wkvT, *p_wupT, *p_woT;
    __half *p_qall, *p_kv, *p_up, *p_ao;
    cudaGetSymbolAddress((void**)&p_xh,   g_xh);
    cudaGetSymbolAddress((void**)&p_wqT,  g_wqT);
    cudaGetSymbolAddress((void**)&p_wkvT, g_wkvT);
    cudaGetSymbolAddress((void**)&p_wupT, g_wupT);
    cudaGetSymbolAddress((void**)&p_woT,  g_woT);
    cudaGetSymbolAddress((void**)&p_qall, g_qallh);
    cudaGetSymbolAddress((void**)&p_kv,   g_kvh);
    cudaGetSymbolAddress((void**)&p_up,   g_uph);
    cudaGetSymbolAddress((void**)&p_ao,   g_AOh);

    static bool inited = false;
    static cudaStream_t s1, s2;
    static cudaEvent_t eStart, eF2h, eUp, eWo;
    if (!inited) {
        cudaStreamCreateWithFlags(&s1, cudaStreamNonBlocking);
        cudaStreamCreateWithFlags(&s2, cudaStreamNonBlocking);
        cudaEventCreateWithFlags(&eStart, cudaEventDisableTiming);
        cudaEventCreateWithFlags(&eF2h,   cudaEventDisableTiming);
        cudaEventCreateWithFlags(&eUp,    cudaEventDisableTiming);
        cudaEventCreateWithFlags(&eWo,    cudaEventDisableTiming);
        cudaFuncSetAttribute(flash_attn_kernel,
                             cudaFuncAttributeMaxDynamicSharedMemorySize, FSMEM);
        cudaFuncSetAttribute((const void*)tgemm_h4<128, 64, 32, false>,
                             cudaFuncAttributeMaxDynamicSharedMemorySize, SM4_G128);
        cudaFuncSetAttribute((const void*)tgemm_h4<64, 32, 32, false>,
                             cudaFuncAttributeMaxDynamicSharedMemorySize, SM4_G64);
        cudaFuncSetAttribute((const void*)tgemm_h4<128, 64, 32, true>,
                             cudaFuncAttributeMaxDynamicSharedMemorySize, SM4_G128);
        inited = true;
    }

    const float scale = 1.0f / sqrtf((float)cDQK);
    dim3 tblk(32, 8);

    // fork side streams off the capture (default) stream
    cudaEventRecord(eStart, 0);
    cudaStreamWaitEvent(s1, eStart, 0);
    cudaStreamWaitEvent(s2, eStart, 0);

    // ---- main stream: x->half, T(wq), wq GEMM ----
    f2h_kernel<<<(unsigned)(((size_t)cM * cE / 8 + 255) / 256), 256>>>(x, p_xh, (size_t)cM * cE);
    cudaEventRecord(eF2h, 0);
    transpose_h_kernel<<<dim3(cNQ / 32, cE / 64), tblk>>>(wq, p_wqT, cE, cNQ);
    tgemm_h4<128, 64, 32, false><<<PGRID, 256, SM4_G128>>>(
        p_xh, p_wqT, p_qall, cE, cE, cE, cNQ, cM / 128, cNQ / 128);
    rope_q_kernel<<<(cM * cH * (cRD / 2) + 255) / 256, 256>>>(cosT, sinT);

    // ---- side stream s1: kv chain -> up GEMM ----
    transpose_h_kernel<<<dim3(cNKV / 32, cE / 64), tblk, 0, s1>>>(wkvd, p_wkvT, cE, cNKV);
    transpose_h_kernel<<<dim3(cNUP / 32, cRK / 64), tblk, 0, s1>>>(wup, p_wupT, cRK, cNUP);
    cudaStreamWaitEvent(s1, eF2h, 0);
    tgemm_h4<64, 32, 32, false><<<PGRID, 256, SM4_G64, s1>>>(
        p_xh, p_wkvT, p_kv, cE, cE, cE, cNKV, cM / 128, cNKV / 64);
    rope_k_kernel<<<(cM * (cRD / 2) + 255) / 256, 256, 0, s1>>>(cosT, sinT);
    tgemm_h4<128, 64, 32, false><<<PGRID, 256, SM4_G128, s1>>>(
        p_kv, p_wupT, p_up, cRK, cNKV, cRK, cNUP, cM / 128, cNUP / 128);
    cudaEventRecord(eUp, s1);

    // ---- side stream s2: T(wout) ----
    transpose_h_kernel<<<dim3(cE / 32, cNQ / 64), tblk, 0, s2>>>(wout, p_woT, cNQ, cE);
    cudaEventRecord(eWo, s2);

    // ---- join: flash needs rope_q (main) + rope_k/up (s1) ----
    cudaStreamWaitEvent(0, eUp, 0);
    flash_attn_kernel<<<dim3(cL / FBR, cBH), 256, FSMEM>>>(scale);

    // ---- final GEMM needs flash (main) + woT (s2) ----
    cudaStreamWaitEvent(0, eWo, 0);
    tgemm_h4<128, 64, 32, true><<<PGRID, 256, SM4_G128>>>(
        p_ao, p_woT, out, cNQ, cNQ, cNQ, cE, cM / 128, cE / 128);
}